// round 4
// baseline (speedup 1.0000x reference)
#include <cuda_runtime.h>
#include <cuda_fp16.h>
#include <cstdint>

// GRU decoder, H=4096, T=2048. Persistent single kernel + software grid barrier.
// R2: fp16 weight scratch (100.7 MB) -> fits L2.
// R4: 32B ld.global.L2::evict_last.v4.b64 weight loads (sm_103 requires 32B for
//     evict_last), Stage-B deferred pre-barrier from smem, prefetch double-buffer.

#define HDIM 4096
#define IN_DIM 400
#define OROWS 401
#define NOUT 400
#define WARPS_PER_BLOCK 28
#define NTHREADS (WARPS_PER_BLOCK * 32)

// ---- device scratch (static: no runtime allocations allowed) ----
__device__ __half g_whh_h[(size_t)3 * HDIM * HDIM];   // 100.7 MB fp16 W_hh
__device__ __half g_wout_h[(size_t)OROWS * HDIM];     // 3.3 MB fp16 W_out
__device__ float g_h[2][HDIM];                        // double-buffered hidden state
__device__ float g_gx[3 * HDIM];                      // W_ih @ relu(x) + b_ih
__device__ unsigned g_cnt;                            // grid barrier arrive counter
__device__ unsigned g_gen;                            // grid barrier generation

__device__ __forceinline__ float warp_sum(float v) {
#pragma unroll
    for (int o = 16; o; o >>= 1) v += __shfl_xor_sync(0xffffffffu, v, o);
    return v;
}

// Sense-reversing grid barrier; all blocks co-resident (grid == #SMs, 1 blk/SM).
__device__ __forceinline__ void grid_sync() {
    __syncthreads();
    if (threadIdx.x == 0) {
        __threadfence();
        unsigned gen = *(volatile unsigned*)&g_gen;
        unsigned nblk = gridDim.x;
        if (atomicAdd(&g_cnt, 1u) == nblk - 1u) {
            atomicExch(&g_cnt, 0u);
            __threadfence();
            atomicAdd(&g_gen, 1u);
        } else {
            while (*(volatile unsigned*)&g_gen == gen) { }  // tight spin (L2 poll)
        }
        __threadfence();
    }
    __syncthreads();
}

__device__ __forceinline__ float sigmoidf_(float x) { return 1.0f / (1.0f + expf(-x)); }

// 32-byte fp16 weight load (16 halves) with L2 evict_last residency hint.
// sm_103 ptxas only accepts evict_last on .v8.b32 / .v4.b64.
struct W32 { unsigned long long a, b, c, d; };
__device__ __forceinline__ W32 ldg_el32(const __half* p) {
    W32 v;
    asm("ld.global.L2::evict_last.v4.b64 {%0,%1,%2,%3}, [%4];"
        : "=l"(v.a), "=l"(v.b), "=l"(v.c), "=l"(v.d) : "l"(p));
    return v;
}

// dot of 4 fp16 (packed in u64) with 4 fp32 h values
__device__ __forceinline__ float dot4(unsigned long long u, float4 h) {
    float2 p0 = __half22float2(*(const __half2*)&u);
    float2 p1 = __half22float2(*((const __half2*)&u + 1));
    return p0.x * h.x + p0.y * h.y + p1.x * h.z + p1.y * h.w;
}

// dot of 16 fp16 weights with 16 fp32 h values (h4 = 4 consecutive float4)
__device__ __forceinline__ float dot16(const W32& w, const float4* h4) {
    return (dot4(w.a, h4[0]) + dot4(w.b, h4[1]))
         + (dot4(w.c, h4[2]) + dot4(w.d, h4[3]));
}

__global__ void __launch_bounds__(NTHREADS, 1)
decoder_persistent_kernel(const float* __restrict__ start,
                          const float* __restrict__ enc,
                          const float* __restrict__ W_ih,
                          const float* __restrict__ W_hh,
                          const float* __restrict__ b_ih,
                          const float* __restrict__ b_hh,
                          const float* __restrict__ W_out,
                          const float* __restrict__ b_out,
                          const int*   __restrict__ maxlen_ptr,
                          float* __restrict__ out)
{
    __shared__ float h_s[HDIM];

    const int lane   = threadIdx.x & 31;
    const int warp   = threadIdx.x >> 5;
    const int gwarp  = blockIdx.x * WARPS_PER_BLOCK + warp;
    const int gwarps = gridDim.x * WARPS_PER_BLOCK;
    const int gtid    = blockIdx.x * NTHREADS + threadIdx.x;
    const int gthreads = gridDim.x * NTHREADS;
    const int T = maxlen_ptr ? *maxlen_ptr : 2048;

    // ---- convert W_hh, W_out to fp16 scratch (every launch; deterministic) ----
    {
        const size_t total = (size_t)3 * HDIM * HDIM;
        for (size_t idx = (size_t)gtid * 4; idx < total; idx += (size_t)gthreads * 4) {
            float4 v = *(const float4*)(W_hh + idx);
            __half2* dst = (__half2*)(g_whh_h + idx);
            dst[0] = __floats2half2_rn(v.x, v.y);
            dst[1] = __floats2half2_rn(v.z, v.w);
        }
        const size_t ototal = (size_t)OROWS * HDIM;
        for (size_t idx = (size_t)gtid * 4; idx < ototal; idx += (size_t)gthreads * 4) {
            float4 v = *(const float4*)(W_out + idx);
            __half2* dst = (__half2*)(g_wout_h + idx);
            dst[0] = __floats2half2_rn(v.x, v.y);
            dst[1] = __floats2half2_rn(v.z, v.w);
        }
    }

    // ---- init: h0 = encoder_hidden ----
    for (int idx = gtid; idx < HDIM; idx += gthreads)
        g_h[0][idx] = enc[idx];

    // ---- gx = W_ih @ relu(start) + b_ih (once per launch, fp32) ----
    for (int r = gwarp; r < 3 * HDIM; r += gwarps) {
        const float* wr = W_ih + (size_t)r * IN_DIM;
        float acc = 0.f;
        for (int k = lane; k < IN_DIM; k += 32) {
            float x = start[k];
            x = x > 0.f ? x : 0.f;
            acc += wr[k] * x;
        }
        acc = warp_sum(acc);
        if (lane == 0) g_gx[r] = acc + b_ih[r];
    }
    grid_sync();

    // Stage-B row mapping: spread 401 W_out rows evenly across all SMs
    int spread = gwarps / OROWS;
    if (spread < 1) spread = 1;
    int brow = -1;
    if ((gwarp % spread) == 0 && (gwarp / spread) < OROWS) brow = gwarp / spread;

    // my Stage-A row (fixed for the whole launch; <= 1 row per warp)
    const int myrow = (gwarp < HDIM) ? gwarp : -1;

    // ---- main recurrence ----
    // Step t: stage h_s = h(t) = h_new(t-1); StageA computes h(t+1);
    //         StageB(t-1) (deferred) reads h_new(t-1) straight from h_s; barrier.
    for (int t = 0; t < T; t++) {
        const float* __restrict__ hc = g_h[t & 1];
        float* __restrict__ hn = g_h[(t + 1) & 1];

        // stage h_cur into shared memory (vectorized)
        {
            const float4* src = (const float4*)hc;
            float4* dst = (float4*)h_s;
            for (int idx = threadIdx.x; idx < HDIM / 4; idx += NTHREADS)
                dst[idx] = src[idx];
        }
        __syncthreads();

        // Stage A: one warp per output i, three fp16 row dots + gate math.
        // Per lane: 16 halves (32B) per load, 8 iterations cover the 4096-row.
        if (myrow >= 0) {
            const int i = myrow;
            const __half* w0 = g_whh_h + (size_t)i * HDIM;
            const __half* w1 = g_whh_h + ((size_t)i + HDIM) * HDIM;
            const __half* w2 = g_whh_h + ((size_t)i + 2 * HDIM) * HDIM;
            const float4* h4 = (const float4*)h_s;
            float a0 = 0.f, a1 = 0.f, a2 = 0.f;

            int k = lane * 16;                 // half index; iter stride 512
            W32 c0 = ldg_el32(w0 + k);
            W32 c1 = ldg_el32(w1 + k);
            W32 c2 = ldg_el32(w2 + k);
#pragma unroll
            for (int it = 0; it < 8; it++) {
                int kn = k + 512;
                W32 n0, n1, n2;
                if (it < 7) {
                    n0 = ldg_el32(w0 + kn);
                    n1 = ldg_el32(w1 + kn);
                    n2 = ldg_el32(w2 + kn);
                }
                const float4* hp = h4 + (k >> 2);
                a0 += dot16(c0, hp);
                a1 += dot16(c1, hp);
                a2 += dot16(c2, hp);
                c0 = n0; c1 = n1; c2 = n2;
                k = kn;
            }
            a0 = warp_sum(a0);
            a1 = warp_sum(a1);
            a2 = warp_sum(a2);
            if (lane == 0) {
                float ghr = a0 + b_hh[i];
                float ghz = a1 + b_hh[i + HDIM];
                float ghn = a2 + b_hh[i + 2 * HDIM];
                float r = sigmoidf_(g_gx[i] + ghr);
                float z = sigmoidf_(g_gx[i + HDIM] + ghz);
                float n = tanhf(g_gx[i + 2 * HDIM] + r * ghn);
                hn[i] = (1.f - z) * n + z * h_s[i];
            }
        }

        // Stage B (deferred, for step t-1): h_new(t-1) == h_s. Pre-barrier,
        // overlaps other blocks' Stage A; h read from smem.
        if (t > 0 && brow >= 0) {
            const __half* wr = g_wout_h + (size_t)brow * HDIM;
            const float4* h4 = (const float4*)h_s;
            float acc = 0.f;
#pragma unroll
            for (int it = 0; it < 8; it++) {
                int k = (it * 32 + lane) * 16;
                W32 u = ldg_el32(wr + k);
                acc += dot16(u, h4 + (k >> 2));
            }
            acc = warp_sum(acc);
            if (lane == 0) {
                float o = acc + b_out[brow];
                int tt = t - 1;
                if (brow < NOUT)
                    out[(size_t)tt * NOUT + brow] = tanhf(o);
                else
                    out[(size_t)T * NOUT + tt] = sigmoidf_(o);
            }
        }

        grid_sync();  // h_new(t) globally visible; next step may overwrite old buffer
    }

    // ---- final Stage B for step T-1 (h_new(T-1) = g_h[T&1], visible post-barrier) ----
    if (brow >= 0) {
        const float* hf = g_h[T & 1];
        const __half* wr = g_wout_h + (size_t)brow * HDIM;
        const float4* h4 = (const float4*)hf;
        float acc = 0.f;
#pragma unroll
        for (int it = 0; it < 8; it++) {
            int k = (it * 32 + lane) * 16;
            W32 u = ldg_el32(wr + k);
            acc += dot16(u, h4 + (k >> 2));
        }
        acc = warp_sum(acc);
        if (lane == 0) {
            float o = acc + b_out[brow];
            int tt = T - 1;
            if (brow < NOUT)
                out[(size_t)tt * NOUT + brow] = tanhf(o);
            else
                out[(size_t)T * NOUT + tt] = sigmoidf_(o);
        }
    }
}

extern "C" void kernel_launch(void* const* d_in, const int* in_sizes, int n_in,
                              void* d_out, int out_size) {
    (void)in_sizes; (void)out_size;

    int dev = 0;
    cudaGetDevice(&dev);
    int sm = 148;
    cudaDeviceGetAttribute(&sm, cudaDevAttrMultiProcessorCount, dev);
    if (sm < 1) sm = 148;
    if (sm > 512) sm = 512;

    const float* start = (const float*)d_in[0];
    const float* enc   = (const float*)d_in[1];
    const float* W_ih  = (const float*)d_in[2];
    const float* W_hh  = (const float*)d_in[3];
    const float* b_ih  = (const float*)d_in[4];
    const float* b_hh  = (const float*)d_in[5];
    const float* W_out = (const float*)d_in[6];
    const float* b_out = (const float*)d_in[7];
    const int* maxlen  = (n_in > 8) ? (const int*)d_in[8] : nullptr;

    decoder_persistent_kernel<<<sm, NTHREADS>>>(
        start, enc, W_ih, W_hh, b_ih, b_hh, W_out, b_out, maxlen, (float*)d_out);
}

// round 5
// speedup vs baseline: 1.1775x; 1.1775x over previous
#include <cuda_runtime.h>
#include <cuda_fp16.h>
#include <cstdint>

// GRU decoder, H=4096, T=2048. Persistent single kernel + software grid barrier.
// R2: fp16 weight scratch (100.7 MB) -> fits (mostly) in L2.
// R5: revert evict_last/32B (measured regression), keep deferred Stage-B from
//     smem, explicit distance-1 prefetch double-buffer on 16B streams,
//     fast approx gate math (tanh.approx / ex2.approx), hoisted per-row consts.

#define HDIM 4096
#define IN_DIM 400
#define OROWS 401
#define NOUT 400
#define WARPS_PER_BLOCK 28
#define NTHREADS (WARPS_PER_BLOCK * 32)

__device__ __half g_whh_h[(size_t)3 * HDIM * HDIM];   // 100.7 MB fp16 W_hh
__device__ __half g_wout_h[(size_t)OROWS * HDIM];     // 3.3 MB fp16 W_out
__device__ float g_h[2][HDIM];
__device__ float g_gx[3 * HDIM];
__device__ unsigned g_cnt;
__device__ unsigned g_gen;

__device__ __forceinline__ float warp_sum(float v) {
#pragma unroll
    for (int o = 16; o; o >>= 1) v += __shfl_xor_sync(0xffffffffu, v, o);
    return v;
}

__device__ __forceinline__ void grid_sync() {
    __syncthreads();
    if (threadIdx.x == 0) {
        __threadfence();
        unsigned gen = *(volatile unsigned*)&g_gen;
        unsigned nblk = gridDim.x;
        if (atomicAdd(&g_cnt, 1u) == nblk - 1u) {
            atomicExch(&g_cnt, 0u);
            __threadfence();
            atomicAdd(&g_gen, 1u);
        } else {
            while (*(volatile unsigned*)&g_gen == gen) { }
        }
        __threadfence();
    }
    __syncthreads();
}

__device__ __forceinline__ float fast_sigmoid(float x) {
    float e;
    asm("ex2.approx.f32 %0, %1;" : "=f"(e) : "f"(-1.4426950408889634f * x));
    float r;
    asm("rcp.approx.f32 %0, %1;" : "=f"(r) : "f"(1.0f + e));
    return r;
}
__device__ __forceinline__ float fast_tanh(float x) {
    float r;
    asm("tanh.approx.f32 %0, %1;" : "=f"(r) : "f"(x));
    return r;
}

__device__ __forceinline__ float dot8(uint4 u, float4 hA, float4 hB) {
    float2 p; float s0 = 0.f, s1 = 0.f;
    p = __half22float2(*(const __half2*)&u.x); s0 += p.x * hA.x; s1 += p.y * hA.y;
    p = __half22float2(*(const __half2*)&u.y); s0 += p.x * hA.z; s1 += p.y * hA.w;
    p = __half22float2(*(const __half2*)&u.z); s0 += p.x * hB.x; s1 += p.y * hB.y;
    p = __half22float2(*(const __half2*)&u.w); s0 += p.x * hB.z; s1 += p.y * hB.w;
    return s0 + s1;
}

__global__ void __launch_bounds__(NTHREADS, 1)
decoder_persistent_kernel(const float* __restrict__ start,
                          const float* __restrict__ enc,
                          const float* __restrict__ W_ih,
                          const float* __restrict__ W_hh,
                          const float* __restrict__ b_ih,
                          const float* __restrict__ b_hh,
                          const float* __restrict__ W_out,
                          const float* __restrict__ b_out,
                          const int*   __restrict__ maxlen_ptr,
                          float* __restrict__ out)
{
    __shared__ float h_s[HDIM];

    const int lane   = threadIdx.x & 31;
    const int warp   = threadIdx.x >> 5;
    const int gwarp  = blockIdx.x * WARPS_PER_BLOCK + warp;
    const int gwarps = gridDim.x * WARPS_PER_BLOCK;
    const int gtid    = blockIdx.x * NTHREADS + threadIdx.x;
    const int gthreads = gridDim.x * NTHREADS;
    const int T = maxlen_ptr ? *maxlen_ptr : 2048;

    // ---- convert W_hh, W_out to fp16 scratch ----
    {
        const size_t total = (size_t)3 * HDIM * HDIM;
        for (size_t idx = (size_t)gtid * 4; idx < total; idx += (size_t)gthreads * 4) {
            float4 v = *(const float4*)(W_hh + idx);
            __half2* dst = (__half2*)(g_whh_h + idx);
            dst[0] = __floats2half2_rn(v.x, v.y);
            dst[1] = __floats2half2_rn(v.z, v.w);
        }
        const size_t ototal = (size_t)OROWS * HDIM;
        for (size_t idx = (size_t)gtid * 4; idx < ototal; idx += (size_t)gthreads * 4) {
            float4 v = *(const float4*)(W_out + idx);
            __half2* dst = (__half2*)(g_wout_h + idx);
            dst[0] = __floats2half2_rn(v.x, v.y);
            dst[1] = __floats2half2_rn(v.z, v.w);
        }
    }

    for (int idx = gtid; idx < HDIM; idx += gthreads)
        g_h[0][idx] = enc[idx];

    for (int r = gwarp; r < 3 * HDIM; r += gwarps) {
        const float* wr = W_ih + (size_t)r * IN_DIM;
        float acc = 0.f;
        for (int k = lane; k < IN_DIM; k += 32) {
            float x = start[k];
            x = x > 0.f ? x : 0.f;
            acc += wr[k] * x;
        }
        acc = warp_sum(acc);
        if (lane == 0) g_gx[r] = acc + b_ih[r];
    }
    grid_sync();

    int spread = gwarps / OROWS;
    if (spread < 1) spread = 1;
    int brow = -1;
    if ((gwarp % spread) == 0 && (gwarp / spread) < OROWS) brow = gwarp / spread;

    const int myrow = (gwarp < HDIM) ? gwarp : -1;

    // hoist per-row constants out of the time loop
    float c_br = 0.f, c_bz = 0.f, c_bn = 0.f, c_gr = 0.f, c_gz = 0.f, c_gn = 0.f;
    if (myrow >= 0) {
        c_br = b_hh[myrow];
        c_bz = b_hh[myrow + HDIM];
        c_bn = b_hh[myrow + 2 * HDIM];
        c_gr = g_gx[myrow];
        c_gz = g_gx[myrow + HDIM];
        c_gn = g_gx[myrow + 2 * HDIM];
    }
    const float c_bo = (brow >= 0) ? b_out[brow] : 0.f;

    for (int t = 0; t < T; t++) {
        const float* __restrict__ hc = g_h[t & 1];
        float* __restrict__ hn = g_h[(t + 1) & 1];

        {
            const float4* src = (const float4*)hc;
            float4* dst = (float4*)h_s;
            for (int idx = threadIdx.x; idx < HDIM / 4; idx += NTHREADS)
                dst[idx] = src[idx];
        }
        __syncthreads();

        if (myrow >= 0) {
            const int i = myrow;
            const uint4* w0 = (const uint4*)(g_whh_h + (size_t)i * HDIM);
            const uint4* w1 = (const uint4*)(g_whh_h + ((size_t)i + HDIM) * HDIM);
            const uint4* w2 = (const uint4*)(g_whh_h + ((size_t)i + 2 * HDIM) * HDIM);
            const float4* h4 = (const float4*)h_s;
            float a0 = 0.f, a1 = 0.f, a2 = 0.f;

            int k = lane;
            uint4 c0 = w0[k];
            uint4 c1 = w1[k];
            uint4 c2 = w2[k];
#pragma unroll
            for (int it = 0; it < 16; it++) {
                uint4 n0, n1, n2;
                if (it < 15) {
                    n0 = w0[k + 32];
                    n1 = w1[k + 32];
                    n2 = w2[k + 32];
                }
                float4 hA = h4[2 * k];
                float4 hB = h4[2 * k + 1];
                a0 += dot8(c0, hA, hB);
                a1 += dot8(c1, hA, hB);
                a2 += dot8(c2, hA, hB);
                c0 = n0; c1 = n1; c2 = n2;
                k += 32;
            }
            a0 = warp_sum(a0);
            a1 = warp_sum(a1);
            a2 = warp_sum(a2);
            float r = fast_sigmoid(c_gr + a0 + c_br);
            float z = fast_sigmoid(c_gz + a1 + c_bz);
            float n = fast_tanh(c_gn + r * (a2 + c_bn));
            if (lane == 0) {
                hn[i] = (1.f - z) * n + z * h_s[i];
            }
        }

        if (t > 0 && brow >= 0) {
            const uint4* wr = (const uint4*)(g_wout_h + (size_t)brow * HDIM);
            const float4* h4 = (const float4*)h_s;
            float acc = 0.f;
#pragma unroll 4
            for (int k = lane; k < HDIM / 8; k += 32) {
                uint4 u = wr[k];
                acc += dot8(u, h4[2 * k], h4[2 * k + 1]);
            }
            acc = warp_sum(acc);
            if (lane == 0) {
                float o = acc + c_bo;
                int tt = t - 1;
                if (brow < NOUT)
                    out[(size_t)tt * NOUT + brow] = fast_tanh(o);
                else
                    out[(size_t)T * NOUT + tt] = fast_sigmoid(o);
            }
        }

        grid_sync();
    }

    if (brow >= 0) {
        const float* hf = g_h[T & 1];
        const uint4* wr = (const uint4*)(g_wout_h + (size_t)brow * HDIM);
        const float4* h4 = (const float4*)hf;
        float acc = 0.f;
#pragma unroll 4
        for (int k = lane; k < HDIM / 8; k += 32) {
            uint4 u = wr[k];
            acc += dot8(u, h4[2 * k], h4[2 * k + 1]);
        }
        acc = warp_sum(acc);
        if (lane == 0) {
            float o = acc + c_bo;
            int tt = T - 1;
            if (brow < NOUT)
                out[(size_t)tt * NOUT + brow] = fast_tanh(o);
            else
                out[(size_t)T * NOUT + tt] = fast_sigmoid(o);
        }
    }
}

extern "C" void kernel_launch(void* const* d_in, const int* in_sizes, int n_in,
                              void* d_out, int out_size) {
    (void)in_sizes; (void)out_size;

    int dev = 0;
    cudaGetDevice(&dev);
    int sm = 148;
    cudaDeviceGetAttribute(&sm, cudaDevAttrMultiProcessorCount, dev);
    if (sm < 1) sm = 148;
    if (sm > 512) sm = 512;

    const float* start = (const float*)d_in[0];
    const float* enc   = (const float*)d_in[1];
    const float* W_ih  = (const float*)d_in[2];
    const float* W_hh  = (const float*)d_in[3];
    const float* b_ih  = (const float*)d_in[4];
    const float* b_hh  = (const float*)d_in[5];
    const float* W_out = (const float*)d_in[6];
    const float* b_out = (const float*)d_in[7];
    const int* maxlen  = (n_in > 8) ? (const int*)d_in[8] : nullptr;

    decoder_persistent_kernel<<<sm, NTHREADS>>>(
        start, enc, W_ih, W_hh, b_ih, b_hh, W_out, b_out, maxlen, (float*)d_out);
}

// round 6
// speedup vs baseline: 1.3372x; 1.1356x over previous
#include <cuda_runtime.h>
#include <cuda_fp16.h>
#include <cstdint>

// GRU decoder, H=4096, T=2048. Persistent single kernel + software grid barrier.
// R2: fp16 weight scratch (100.7 MB) -> L2-resident working set.  [25.68 ms]
// R4/R5 lesson: hand-rolled distance-1 prefetch LOWERS MLP (3 loads in flight
//   vs ptxas's 12 for the batched unroll loop) -> regression. Revert to
//   compiler-scheduled batched loads, raise unroll to 8 (24 LDGs per batch).
// R6 keeps from R5: fast approx gates, deferred Stage-B from smem, hoisted
//   per-row constants, nanosleep spin.

#define HDIM 4096
#define IN_DIM 400
#define OROWS 401
#define NOUT 400
#define WARPS_PER_BLOCK 28
#define NTHREADS (WARPS_PER_BLOCK * 32)

__device__ __half g_whh_h[(size_t)3 * HDIM * HDIM];   // 100.7 MB fp16 W_hh
__device__ __half g_wout_h[(size_t)OROWS * HDIM];     // 3.3 MB fp16 W_out
__device__ float g_h[2][HDIM];                        // double-buffered hidden state
__device__ float g_gx[3 * HDIM];                      // W_ih @ relu(x) + b_ih
__device__ unsigned g_cnt;
__device__ unsigned g_gen;

__device__ __forceinline__ float warp_sum(float v) {
#pragma unroll
    for (int o = 16; o; o >>= 1) v += __shfl_xor_sync(0xffffffffu, v, o);
    return v;
}

// Sense-reversing grid barrier; all blocks co-resident (grid == #SMs, 1 blk/SM).
__device__ __forceinline__ void grid_sync() {
    __syncthreads();
    if (threadIdx.x == 0) {
        __threadfence();
        unsigned gen = *(volatile unsigned*)&g_gen;
        unsigned nblk = gridDim.x;
        if (atomicAdd(&g_cnt, 1u) == nblk - 1u) {
            atomicExch(&g_cnt, 0u);
            __threadfence();
            atomicAdd(&g_gen, 1u);
        } else {
            while (*(volatile unsigned*)&g_gen == gen) { __nanosleep(32); }
        }
        __threadfence();
    }
    __syncthreads();
}

// fast gates: |err| ~1e-5, negligible vs fp16 weight quantization (2.8e-4)
__device__ __forceinline__ float fast_sigmoid(float x) {
    float e;
    asm("ex2.approx.f32 %0, %1;" : "=f"(e) : "f"(-1.4426950408889634f * x));
    float r;
    asm("rcp.approx.f32 %0, %1;" : "=f"(r) : "f"(1.0f + e));
    return r;
}
__device__ __forceinline__ float fast_tanh(float x) {
    float r;
    asm("tanh.approx.f32 %0, %1;" : "=f"(r) : "f"(x));
    return r;
}

// dot of 8 fp16 weights (as uint4) with 8 fp32 h values, fp32 accumulate
__device__ __forceinline__ float dot8(uint4 u, float4 hA, float4 hB) {
    float2 p; float s0 = 0.f, s1 = 0.f;
    p = __half22float2(*(const __half2*)&u.x); s0 += p.x * hA.x; s1 += p.y * hA.y;
    p = __half22float2(*(const __half2*)&u.y); s0 += p.x * hA.z; s1 += p.y * hA.w;
    p = __half22float2(*(const __half2*)&u.z); s0 += p.x * hB.x; s1 += p.y * hB.y;
    p = __half22float2(*(const __half2*)&u.w); s0 += p.x * hB.z; s1 += p.y * hB.w;
    return s0 + s1;
}

__global__ void __launch_bounds__(NTHREADS, 1)
decoder_persistent_kernel(const float* __restrict__ start,
                          const float* __restrict__ enc,
                          const float* __restrict__ W_ih,
                          const float* __restrict__ W_hh,
                          const float* __restrict__ b_ih,
                          const float* __restrict__ b_hh,
                          const float* __restrict__ W_out,
                          const float* __restrict__ b_out,
                          const int*   __restrict__ maxlen_ptr,
                          float* __restrict__ out)
{
    __shared__ float h_s[HDIM];

    const int lane   = threadIdx.x & 31;
    const int warp   = threadIdx.x >> 5;
    const int gwarp  = blockIdx.x * WARPS_PER_BLOCK + warp;
    const int gwarps = gridDim.x * WARPS_PER_BLOCK;
    const int gtid    = blockIdx.x * NTHREADS + threadIdx.x;
    const int gthreads = gridDim.x * NTHREADS;
    const int T = maxlen_ptr ? *maxlen_ptr : 2048;

    // ---- convert W_hh, W_out to fp16 scratch (every launch; deterministic) ----
    {
        const size_t total = (size_t)3 * HDIM * HDIM;
        for (size_t idx = (size_t)gtid * 4; idx < total; idx += (size_t)gthreads * 4) {
            float4 v = *(const float4*)(W_hh + idx);
            __half2* dst = (__half2*)(g_whh_h + idx);
            dst[0] = __floats2half2_rn(v.x, v.y);
            dst[1] = __floats2half2_rn(v.z, v.w);
        }
        const size_t ototal = (size_t)OROWS * HDIM;
        for (size_t idx = (size_t)gtid * 4; idx < ototal; idx += (size_t)gthreads * 4) {
            float4 v = *(const float4*)(W_out + idx);
            __half2* dst = (__half2*)(g_wout_h + idx);
            dst[0] = __floats2half2_rn(v.x, v.y);
            dst[1] = __floats2half2_rn(v.z, v.w);
        }
    }

    // ---- init: h0 = encoder_hidden ----
    for (int idx = gtid; idx < HDIM; idx += gthreads)
        g_h[0][idx] = enc[idx];

    // ---- gx = W_ih @ relu(start) + b_ih (once per launch, fp32) ----
    for (int r = gwarp; r < 3 * HDIM; r += gwarps) {
        const float* wr = W_ih + (size_t)r * IN_DIM;
        float acc = 0.f;
        for (int k = lane; k < IN_DIM; k += 32) {
            float x = start[k];
            x = x > 0.f ? x : 0.f;
            acc += wr[k] * x;
        }
        acc = warp_sum(acc);
        if (lane == 0) g_gx[r] = acc + b_ih[r];
    }
    grid_sync();

    // Stage-B row mapping: spread 401 W_out rows evenly across all SMs
    int spread = gwarps / OROWS;
    if (spread < 1) spread = 1;
    int brow = -1;
    if ((gwarp % spread) == 0 && (gwarp / spread) < OROWS) brow = gwarp / spread;

    // my Stage-A row (fixed for the whole launch; <= 1 row per warp)
    const int myrow = (gwarp < HDIM) ? gwarp : -1;

    // hoist per-row constants out of the time loop
    float c_br = 0.f, c_bz = 0.f, c_bn = 0.f, c_gr = 0.f, c_gz = 0.f, c_gn = 0.f;
    if (myrow >= 0) {
        c_br = b_hh[myrow];
        c_bz = b_hh[myrow + HDIM];
        c_bn = b_hh[myrow + 2 * HDIM];
        c_gr = g_gx[myrow];
        c_gz = g_gx[myrow + HDIM];
        c_gn = g_gx[myrow + 2 * HDIM];
    }
    const float c_bo = (brow >= 0) ? b_out[brow] : 0.f;

    // ---- main recurrence ----
    // Step t: stage h_s = h(t) = h_new(t-1); StageA computes h(t+1);
    //         StageB(t-1) (deferred) reads h_new(t-1) from h_s; barrier.
    for (int t = 0; t < T; t++) {
        const float* __restrict__ hc = g_h[t & 1];
        float* __restrict__ hn = g_h[(t + 1) & 1];

        // stage h_cur into shared memory (vectorized)
        {
            const float4* src = (const float4*)hc;
            float4* dst = (float4*)h_s;
            for (int idx = threadIdx.x; idx < HDIM / 4; idx += NTHREADS)
                dst[idx] = src[idx];
        }
        __syncthreads();

        // Stage A: one warp per output i; compiler-scheduled batched loads
        // (unroll 8 -> ptxas front-batches up to 24 LDG.128s per group).
        if (myrow >= 0) {
            const int i = myrow;
            const uint4* w0 = (const uint4*)(g_whh_h + (size_t)i * HDIM);
            const uint4* w1 = (const uint4*)(g_whh_h + ((size_t)i + HDIM) * HDIM);
            const uint4* w2 = (const uint4*)(g_whh_h + ((size_t)i + 2 * HDIM) * HDIM);
            const float4* h4 = (const float4*)h_s;
            float a0 = 0.f, a1 = 0.f, a2 = 0.f;
#pragma unroll 8
            for (int k = lane; k < HDIM / 8; k += 32) {   // 16 iterations
                uint4 u0 = w0[k];
                uint4 u1 = w1[k];
                uint4 u2 = w2[k];
                float4 hA = h4[2 * k];
                float4 hB = h4[2 * k + 1];
                a0 += dot8(u0, hA, hB);
                a1 += dot8(u1, hA, hB);
                a2 += dot8(u2, hA, hB);
            }
            a0 = warp_sum(a0);
            a1 = warp_sum(a1);
            a2 = warp_sum(a2);
            float r = fast_sigmoid(c_gr + a0 + c_br);
            float z = fast_sigmoid(c_gz + a1 + c_bz);
            float n = fast_tanh(c_gn + r * (a2 + c_bn));
            if (lane == 0) {
                hn[i] = (1.f - z) * n + z * h_s[i];
            }
        }

        // Stage B (deferred, for step t-1): h_new(t-1) == h_s; pre-barrier.
        if (t > 0 && brow >= 0) {
            const uint4* wr = (const uint4*)(g_wout_h + (size_t)brow * HDIM);
            const float4* h4 = (const float4*)h_s;
            float acc = 0.f;
#pragma unroll 4
            for (int k = lane; k < HDIM / 8; k += 32) {
                uint4 u = wr[k];
                acc += dot8(u, h4[2 * k], h4[2 * k + 1]);
            }
            acc = warp_sum(acc);
            if (lane == 0) {
                float o = acc + c_bo;
                int tt = t - 1;
                if (brow < NOUT)
                    out[(size_t)tt * NOUT + brow] = fast_tanh(o);
                else
                    out[(size_t)T * NOUT + tt] = fast_sigmoid(o);
            }
        }

        grid_sync();  // h_new(t) globally visible
    }

    // ---- final Stage B for step T-1 ----
    if (brow >= 0) {
        const float* hf = g_h[T & 1];
        const uint4* wr = (const uint4*)(g_wout_h + (size_t)brow * HDIM);
        const float4* h4 = (const float4*)hf;
        float acc = 0.f;
#pragma unroll 4
        for (int k = lane; k < HDIM / 8; k += 32) {
            uint4 u = wr[k];
            acc += dot8(u, h4[2 * k], h4[2 * k + 1]);
        }
        acc = warp_sum(acc);
        if (lane == 0) {
            float o = acc + c_bo;
            int tt = T - 1;
            if (brow < NOUT)
                out[(size_t)tt * NOUT + brow] = fast_tanh(o);
            else
                out[(size_t)T * NOUT + tt] = fast_sigmoid(o);
        }
    }
}

extern "C" void kernel_launch(void* const* d_in, const int* in_sizes, int n_in,
                              void* d_out, int out_size) {
    (void)in_sizes; (void)out_size;

    int dev = 0;
    cudaGetDevice(&dev);
    int sm = 148;
    cudaDeviceGetAttribute(&sm, cudaDevAttrMultiProcessorCount, dev);
    if (sm < 1) sm = 148;
    if (sm > 512) sm = 512;

    const float* start = (const float*)d_in[0];
    const float* enc   = (const float*)d_in[1];
    const float* W_ih  = (const float*)d_in[2];
    const float* W_hh  = (const float*)d_in[3];
    const float* b_ih  = (const float*)d_in[4];
    const float* b_hh  = (const float*)d_in[5];
    const float* W_out = (const float*)d_in[6];
    const float* b_out = (const float*)d_in[7];
    const int* maxlen  = (n_in > 8) ? (const int*)d_in[8] : nullptr;

    decoder_persistent_kernel<<<sm, NTHREADS>>>(
        start, enc, W_ih, W_hh, b_ih, b_hh, W_out, b_out, maxlen, (float*)d_out);
}